// round 1
// baseline (speedup 1.0000x reference)
#include <cuda_runtime.h>
#include <math.h>

// ============================================================================
// QuanvolutionFilter: 4096 x 196 patches, each a 4-wire quantum circuit.
//
// Math: after the data-dependent RY(angle) product-state prep, the rest of the
// circuit (3 StronglyEntanglingLayers) is a FIXED 16x16 complex unitary U.
//   psi_final = U @ psi0,  psi0 real product state from cos/sin(angle/2)
//   <Z_w>     = psi0^T Re(U^H Z_w U) psi0          (real symmetric form)
//   out_k     = psi0^T A_k psi0 + b_k,  A_k = sum_w W[k,w] Re(U^H Z_w U)
//
// Kernel 1 (setup): build U (16 threads, one per column), form packed
//   upper-triangular A_k with off-diagonals doubled -> g_Ap[136][4].
// Kernel 2 (main): one thread per patch: 4 sincos -> psi0[16] -> 136-term
//   quadratic form fused across the 4 outputs (float4 LDS per term).
// ============================================================================

#define N_TRI 136

__device__ __align__(16) float g_Ap[N_TRI * 4];   // [tri_index][k]

__global__ void qsetup(const float* __restrict__ params,   // (3,4,3)
                       const float* __restrict__ W)        // (4,4)
{
    __shared__ float Ur[16][16];   // [row n][col c]
    __shared__ float Ui[16][16];

    int t = threadIdx.x;
    // init identity
    Ur[t >> 4][t & 15] = ((t >> 4) == (t & 15)) ? 1.0f : 0.0f;
    Ui[t >> 4][t & 15] = 0.0f;
    __syncthreads();

    // Build U: 16 threads, each owns one column. Gates act on the row index.
    if (t < 16) {
        int c = t;
        for (int l = 0; l < 3; ++l) {
            // Rot(phi,theta,omega) on each wire
            for (int w = 0; w < 4; ++w) {
                float phi = params[l * 12 + w * 3 + 0];
                float th  = params[l * 12 + w * 3 + 1];
                float om  = params[l * 12 + w * 3 + 2];
                float ct = cosf(0.5f * th), st = sinf(0.5f * th);
                float a  = 0.5f * (phi + om);
                float bb = 0.5f * (phi - om);
                float ca = cosf(a),  sa = sinf(a);
                float cb = cosf(bb), sb = sinf(bb);
                // m00 = e^{-ia} c ; m01 = -e^{+ib} s ; m10 = e^{-ib} s ; m11 = e^{+ia} c
                float m00r =  ca * ct, m00i = -sa * ct;
                float m01r = -cb * st, m01i = -sb * st;
                float m10r =  cb * st, m10i = -sb * st;
                float m11r =  ca * ct, m11i =  sa * ct;
                int mask = 8 >> w;   // wire 0 = MSB of the 4-bit row index
                for (int n = 0; n < 16; ++n) {
                    if (n & mask) continue;
                    int n1 = n | mask;
                    float x0r = Ur[n][c],  x0i = Ui[n][c];
                    float x1r = Ur[n1][c], x1i = Ui[n1][c];
                    Ur[n][c]  = m00r * x0r - m00i * x0i + m01r * x1r - m01i * x1i;
                    Ui[n][c]  = m00r * x0i + m00i * x0r + m01r * x1i + m01i * x1r;
                    Ur[n1][c] = m10r * x0r - m10i * x0i + m11r * x1r - m11i * x1i;
                    Ui[n1][c] = m10r * x0i + m10i * x0r + m11r * x1i + m11i * x1r;
                }
            }
            // CNOT ring, range r = (l % 3) + 1, applied sequentially w=0..3
            int r = (l % 3) + 1;
            for (int w = 0; w < 4; ++w) {
                int ctrl = w, tgt = (w + r) & 3;
                int cmask = 8 >> ctrl, tmask = 8 >> tgt;
                for (int n = 0; n < 16; ++n) {
                    if ((n & cmask) && !(n & tmask)) {
                        int n1 = n | tmask;
                        float tr = Ur[n][c]; Ur[n][c] = Ur[n1][c]; Ur[n1][c] = tr;
                        float ti = Ui[n][c]; Ui[n][c] = Ui[n1][c]; Ui[n1][c] = ti;
                    }
                }
            }
        }
    }
    __syncthreads();

    // Each of 256 threads computes one (i,j); keep upper triangle, double off-diag.
    int i = t >> 4, j = t & 15;
    if (j >= i) {
        float M[4];
        #pragma unroll
        for (int w = 0; w < 4; ++w) {
            int mask = 8 >> w;
            float acc = 0.0f;
            #pragma unroll
            for (int n = 0; n < 16; ++n) {
                float v = Ur[n][i] * Ur[n][j] + Ui[n][i] * Ui[n][j];
                acc += (n & mask) ? -v : v;
            }
            M[w] = acc;
        }
        float scale = (i == j) ? 1.0f : 2.0f;
        int midx = 16 * i - (i * (i - 1)) / 2 + (j - i);   // packed upper-tri index
        #pragma unroll
        for (int k = 0; k < 4; ++k) {
            float v = 0.0f;
            #pragma unroll
            for (int w = 0; w < 4; ++w) v += W[k * 4 + w] * M[w];
            g_Ap[midx * 4 + k] = v * scale;
        }
    }
}

__global__ void __launch_bounds__(256) qmain(const float* __restrict__ x,
                                             const float* __restrict__ bvec,
                                             float* __restrict__ out,
                                             int total)
{
    __shared__ float4 sA[N_TRI];
    __shared__ float  sb[4];
    for (int i = threadIdx.x; i < N_TRI; i += 256)
        sA[i] = reinterpret_cast<const float4*>(g_Ap)[i];
    if (threadIdx.x < 4) sb[threadIdx.x] = bvec[threadIdx.x];
    __syncthreads();

    int gid = blockIdx.x * blockDim.x + threadIdx.x;
    if (gid >= total) return;

    int b  = gid / 196;
    int p  = gid - b * 196;
    int pr = p / 14;
    int pc = p - pr * 14;

    const float* img = x + b * 784 + pr * 56 + pc * 2;
    float a0 = img[0];
    float a1 = img[1];
    float a2 = img[28];
    float a3 = img[29];

    float c0, s0, c1, s1, c2, s2, c3, s3;
    __sincosf(0.5f * a0, &s0, &c0);
    __sincosf(0.5f * a1, &s1, &c1);
    __sincosf(0.5f * a2, &s2, &c2);
    __sincosf(0.5f * a3, &s3, &c3);

    // psi0[i] = f0(b0) f1(b1) f2(b2) f3(b3), i = b0*8+b1*4+b2*2+b3
    float q01[4] = { c0 * c1, c0 * s1, s0 * c1, s0 * s1 };
    float q23[4] = { c2 * c3, c2 * s3, s2 * c3, s2 * s3 };
    float psi[16];
    #pragma unroll
    for (int i = 0; i < 4; ++i)
        #pragma unroll
        for (int j = 0; j < 4; ++j)
            psi[i * 4 + j] = q01[i] * q23[j];

    float acc0 = sb[0], acc1 = sb[1], acc2 = sb[2], acc3 = sb[3];
    int m = 0;
    #pragma unroll
    for (int i = 0; i < 16; ++i) {
        #pragma unroll
        for (int j = i; j < 16; ++j) {
            float tpp = psi[i] * psi[j];
            float4 w = sA[m++];
            acc0 = fmaf(w.x, tpp, acc0);
            acc1 = fmaf(w.y, tpp, acc1);
            acc2 = fmaf(w.z, tpp, acc2);
            acc3 = fmaf(w.w, tpp, acc3);
        }
    }

    // out[b, p*4 + k] with out row = 784 floats  ->  flat index gid*4 + k
    reinterpret_cast<float4*>(out)[gid] = make_float4(acc0, acc1, acc2, acc3);
}

extern "C" void kernel_launch(void* const* d_in, const int* in_sizes, int n_in,
                              void* d_out, int out_size)
{
    const float* x      = (const float*)d_in[0];   // (B,1,28,28)
    const float* params = (const float*)d_in[1];   // (3,4,3)
    const float* W      = (const float*)d_in[2];   // (4,4)
    const float* bvec   = (const float*)d_in[3];   // (4,)
    float* out = (float*)d_out;                    // (B, 784)

    int total = in_sizes[0] / 4;                   // B*784/4 = B*196 patches

    qsetup<<<1, 256>>>(params, W);
    qmain<<<(total + 255) / 256, 256>>>(x, bvec, out, total);
}

// round 3
// speedup vs baseline: 1.7951x; 1.7951x over previous
#include <cuda_runtime.h>
#include <math.h>

// ============================================================================
// QuanvolutionFilter via fixed-unitary reduction + monomial (double-angle)
// basis + packed f32x2 FMA.
//
//   out_k(patch) = m01^T D_k m23 ,   m01 = {1,C0,S0}x{1,C1,S1},
//                                    m23 = {1,C2,S2}x{1,C3,S3},  C=cos(a),S=sin(a)
//   D_k (9x9, padded to 9x10) built once from the circuit unitary U and W,b.
// ============================================================================

#define PACK_F32X2(out, lo, hi) \
    asm("mov.b64 %0, {%1, %2};" : "=l"(out) : "f"(lo), "f"(hi))
#define UNPACK_F32X2(lo, hi, in) \
    asm("mov.b64 {%0, %1}, %2;" : "=f"(lo), "=f"(hi) : "l"(in))
#define MUL_F32X2(out, a, b) \
    asm("mul.rn.f32x2 %0, %1, %2;" : "=l"(out) : "l"(a), "l"(b))
#define FMA_F32X2(d, a, b, c) \
    asm("fma.rn.f32x2 %0, %1, %2, %3;" : "=l"(d) : "l"(a), "l"(b), "l"(c))

// packed coefficients: 45 (u,vp) slots x 2 ulonglong2:
//   slot half0 = (D0[v],D0[v+1],D1[v],D1[v+1]), half1 = (D2..,D3..)
__device__ __align__(16) float g_D[45 * 8];

// E[f][f'][alpha]: coefficient of monomial {1, cos a, sin a}[alpha] in the
// half-angle product p(f,f'), f,f' in {0=cos(a/2),1=sin(a/2)}.
__device__ __forceinline__ float Ecoef(int f, int fp, int al) {
    if (al == 2) return (f != fp) ? 0.5f : 0.0f;   // cs -> sin(a)/2
    if (f != fp) return 0.0f;
    if (al == 0) return 0.5f;                       // cc,ss -> 1/2
    return f ? -0.5f : 0.5f;                        // cc -> +cos/2, ss -> -cos/2
}

__global__ void qsetup(const float* __restrict__ params,   // (3,4,3)
                       const float* __restrict__ W,        // (4,4)
                       const float* __restrict__ bvec)     // (4,)
{
    __shared__ float Ur[16][17];
    __shared__ float Ui[16][17];
    __shared__ float sG[12][8];            // per-gate Rot matrix (r,i x 4)
    __shared__ float sA[4][16][16];        // A_k full symmetric
    __shared__ float sS[4][4][4][9];       // stage-1 partial transform
    __shared__ float sDt[4][9][9];         // D_k[u][v]

    const int t = threadIdx.x;
    const int n = t >> 4, c = t & 15;

    // --- phase A: 12 Rot gate matrices ------------------------------------
    if (t < 12) {
        float phi = params[t * 3 + 0];
        float th  = params[t * 3 + 1];
        float om  = params[t * 3 + 2];
        float ct = cosf(0.5f * th), st = sinf(0.5f * th);
        float a  = 0.5f * (phi + om);
        float bb = 0.5f * (phi - om);
        float ca = cosf(a),  sa = sinf(a);
        float cb = cosf(bb), sb = sinf(bb);
        sG[t][0] =  ca * ct;  sG[t][1] = -sa * ct;   // m00
        sG[t][2] = -cb * st;  sG[t][3] = -sb * st;   // m01
        sG[t][4] =  cb * st;  sG[t][5] = -sb * st;   // m10
        sG[t][6] =  ca * ct;  sG[t][7] =  sa * ct;   // m11
    }
    Ur[n][c] = (n == c) ? 1.0f : 0.0f;
    Ui[n][c] = 0.0f;
    __syncthreads();

    // --- phase B: apply 24 gates to all 16 columns (gather style) ---------
    #pragma unroll
    for (int l = 0; l < 3; ++l) {
        #pragma unroll
        for (int w = 0; w < 4; ++w) {
            const int mask = 8 >> w;                 // wire 0 = MSB of row idx
            const float* g = sG[l * 4 + w];
            float xr = Ur[n][c], xi = Ui[n][c];
            float yr = Ur[n ^ mask][c], yi = Ui[n ^ mask][c];
            float nr, ni;
            if (!(n & mask)) {   // new[n0] = m00*x0 + m01*x1
                nr = g[0]*xr - g[1]*xi + g[2]*yr - g[3]*yi;
                ni = g[0]*xi + g[1]*xr + g[2]*yi + g[3]*yr;
            } else {             // new[n1] = m10*x0 + m11*x1  (y holds x0)
                nr = g[4]*yr - g[5]*yi + g[6]*xr - g[7]*xi;
                ni = g[4]*yi + g[5]*yr + g[6]*xi + g[7]*xr;
            }
            __syncthreads();
            Ur[n][c] = nr; Ui[n][c] = ni;
            __syncthreads();
        }
        const int r = (l % 3) + 1;
        #pragma unroll
        for (int w = 0; w < 4; ++w) {
            const int cm = 8 >> w, tm = 8 >> ((w + r) & 3);
            const int src = (n & cm) ? (n ^ tm) : n;
            float vr = Ur[src][c], vi = Ui[src][c];
            __syncthreads();
            Ur[n][c] = vr; Ui[n][c] = vi;
            __syncthreads();
        }
    }

    // --- phase C: A_k[i][j] = sum_w W[k][w] * Re(U^H Z_w U)[i][j] ----------
    {
        const int i = n, j = c;
        float M[4] = {0.f, 0.f, 0.f, 0.f};
        #pragma unroll
        for (int nn = 0; nn < 16; ++nn) {
            float v = Ur[nn][i] * Ur[nn][j] + Ui[nn][i] * Ui[nn][j];
            #pragma unroll
            for (int w = 0; w < 4; ++w)
                M[w] += (nn & (8 >> w)) ? -v : v;
        }
        #pragma unroll
        for (int k = 0; k < 4; ++k) {
            float acc = 0.0f;
            #pragma unroll
            for (int w = 0; w < 4; ++w) acc += W[k * 4 + w] * M[w];
            sA[k][i][j] = acc;
        }
    }
    __syncthreads();

    // --- phase D stage 1: contract wires 2,3 ------------------------------
    // sS[k][i01][j01][v] = sum_{i23,j23} A_k[i01*4+i23][j01*4+j23]
    //                      * E(i23>>1, j23>>1, v/3) * E(i23&1, j23&1, v%3)
    for (int idx = t; idx < 576; idx += 256) {
        int k   = idx / 144;
        int rem = idx - k * 144;
        int i01 = rem / 36;
        int r2  = rem - i01 * 36;
        int j01 = r2 / 9;
        int v   = r2 - j01 * 9;
        int a2 = v / 3, a3 = v - a2 * 3;
        float acc = 0.0f;
        #pragma unroll
        for (int i23 = 0; i23 < 4; ++i23)
            #pragma unroll
            for (int j23 = 0; j23 < 4; ++j23) {
                float e = Ecoef(i23 >> 1, j23 >> 1, a2) * Ecoef(i23 & 1, j23 & 1, a3);
                acc += e * sA[k][i01 * 4 + i23][j01 * 4 + j23];
            }
        sS[k][i01][j01][v] = acc;
    }
    __syncthreads();

    // --- phase D stage 2: contract wires 0,1; fold bias --------------------
    for (int idx = t; idx < 324; idx += 256) {
        int k  = idx / 81;
        int uv = idx - k * 81;
        int u  = uv / 9;
        int v  = uv - u * 9;
        int a0 = u / 3, a1 = u - a0 * 3;
        float acc = 0.0f;
        #pragma unroll
        for (int i01 = 0; i01 < 4; ++i01)
            #pragma unroll
            for (int j01 = 0; j01 < 4; ++j01) {
                float e = Ecoef(i01 >> 1, j01 >> 1, a0) * Ecoef(i01 & 1, j01 & 1, a1);
                acc += e * sS[k][i01][j01][v];
            }
        if (u == 0 && v == 0) acc += bvec[k];
        sDt[k][u][v] = acc;
    }
    __syncthreads();

    // --- pack: slot (u,vp): half0=(D0[v],D0[v+1],D1[v],D1[v+1]) half1=(D2,D3)
    if (t < 45) {
        int u = t / 5, vp = t - u * 5;
        int v = 2 * vp;
        bool pad = (vp == 4);
        float4* gd = reinterpret_cast<float4*>(g_D);
        gd[t * 2 + 0] = make_float4(sDt[0][u][v], pad ? 0.f : sDt[0][u][v + 1],
                                    sDt[1][u][v], pad ? 0.f : sDt[1][u][v + 1]);
        gd[t * 2 + 1] = make_float4(sDt[2][u][v], pad ? 0.f : sDt[2][u][v + 1],
                                    sDt[3][u][v], pad ? 0.f : sDt[3][u][v + 1]);
    }
}

__global__ void __launch_bounds__(256) qmain(const float* __restrict__ x,
                                             float* __restrict__ out,
                                             int total)
{
    __shared__ ulonglong2 sD[90];
    for (int i = threadIdx.x; i < 90; i += 256)
        sD[i] = reinterpret_cast<const ulonglong2*>(g_D)[i];
    __syncthreads();

    int gid = blockIdx.x * blockDim.x + threadIdx.x;
    if (gid >= total) return;

    int b  = gid / 196;
    int p  = gid - b * 196;
    int pr = p / 14;
    int pc = p - pr * 14;

    const float* img = x + b * 784 + pr * 56 + pc * 2;
    float2 r0 = *reinterpret_cast<const float2*>(img);
    float2 r1 = *reinterpret_cast<const float2*>(img + 28);

    float C0, S0, C1, S1, C2, S2, C3, S3;
    __sincosf(r0.x, &S0, &C0);
    __sincosf(r0.y, &S1, &C1);
    __sincosf(r1.x, &S2, &C2);
    __sincosf(r1.y, &S3, &C3);

    float m01[9] = { 1.0f, C1, S1, C0, C0 * C1, C0 * S1, S0, S0 * C1, S0 * S1 };
    float m23[9] = { 1.0f, C3, S3, C2, C2 * C3, C2 * S3, S2, S2 * C3, S2 * S3 };

    unsigned long long m01b[9], m23p[5];
    #pragma unroll
    for (int u = 0; u < 9; ++u) PACK_F32X2(m01b[u], m01[u], m01[u]);
    #pragma unroll
    for (int vp = 0; vp < 4; ++vp) PACK_F32X2(m23p[vp], m23[2 * vp], m23[2 * vp + 1]);
    {
        float z = 0.0f;
        PACK_F32X2(m23p[4], m23[8], z);
    }

    unsigned long long acc0 = 0ULL, acc1 = 0ULL, acc2 = 0ULL, acc3 = 0ULL;
    #pragma unroll
    for (int u = 0; u < 9; ++u) {
        #pragma unroll
        for (int vp = 0; vp < 5; ++vp) {
            unsigned long long tp;
            MUL_F32X2(tp, m01b[u], m23p[vp]);
            ulonglong2 wa = sD[(u * 5 + vp) * 2 + 0];
            ulonglong2 wb = sD[(u * 5 + vp) * 2 + 1];
            FMA_F32X2(acc0, wa.x, tp, acc0);
            FMA_F32X2(acc1, wa.y, tp, acc1);
            FMA_F32X2(acc2, wb.x, tp, acc2);
            FMA_F32X2(acc3, wb.y, tp, acc3);
        }
    }

    float l0, h0, l1, h1, l2, h2, l3, h3;
    UNPACK_F32X2(l0, h0, acc0);
    UNPACK_F32X2(l1, h1, acc1);
    UNPACK_F32X2(l2, h2, acc2);
    UNPACK_F32X2(l3, h3, acc3);

    reinterpret_cast<float4*>(out)[gid] =
        make_float4(l0 + h0, l1 + h1, l2 + h2, l3 + h3);
}

extern "C" void kernel_launch(void* const* d_in, const int* in_sizes, int n_in,
                              void* d_out, int out_size)
{
    const float* x      = (const float*)d_in[0];   // (B,1,28,28)
    const float* params = (const float*)d_in[1];   // (3,4,3)
    const float* W      = (const float*)d_in[2];   // (4,4)
    const float* bvec   = (const float*)d_in[3];   // (4,)
    float* out = (float*)d_out;                    // (B, 784)

    int total = in_sizes[0] / 4;                   // B*196 patches

    qsetup<<<1, 256>>>(params, W, bvec);
    qmain<<<(total + 255) / 256, 256>>>(x, out, total);
}

// round 5
// speedup vs baseline: 1.9608x; 1.0923x over previous
#include <cuda_runtime.h>
#include <math.h>

// ============================================================================
// QuanvolutionFilter via fixed-unitary reduction + monomial (double-angle)
// basis + packed f32x2 FMA + 2 patches/thread (coefficient-load reuse).
//
//   out_k(patch) = m01^T D_k m23 ,   m01 = {1,C0,S0}x{1,C1,S1},
//                                    m23 = {1,C2,S2}x{1,C3,S3},  C=cos(a),S=sin(a)
//   D_k (9x9, padded to 9x10) built once from the circuit unitary U and W,b.
// ============================================================================

#define PACK_F32X2(out, lo, hi) \
    asm("mov.b64 %0, {%1, %2};" : "=l"(out) : "f"(lo), "f"(hi))
#define UNPACK_F32X2(lo, hi, in) \
    asm("mov.b64 {%0, %1}, %2;" : "=f"(lo), "=f"(hi) : "l"(in))
#define MUL_F32X2(out, a, b) \
    asm("mul.rn.f32x2 %0, %1, %2;" : "=l"(out) : "l"(a), "l"(b))
#define FMA_F32X2(d, a, b, c) \
    asm("fma.rn.f32x2 %0, %1, %2, %3;" : "=l"(d) : "l"(a), "l"(b), "l"(c))

// packed coefficients: 45 (u,vp) slots x 2 ulonglong2:
//   slot half0 = (D0[v],D0[v+1],D1[v],D1[v+1]), half1 = (D2..,D3..)
__device__ __align__(16) float g_D[45 * 8];

// E[f][f'][alpha]: coefficient of monomial {1, cos a, sin a}[alpha] in the
// half-angle product p(f,f'), f,f' in {0=cos(a/2),1=sin(a/2)}.
__device__ __forceinline__ float Ecoef(int f, int fp, int al) {
    if (al == 2) return (f != fp) ? 0.5f : 0.0f;   // cs -> sin(a)/2
    if (f != fp) return 0.0f;
    if (al == 0) return 0.5f;                       // cc,ss -> 1/2
    return f ? -0.5f : 0.5f;                        // cc -> +cos/2, ss -> -cos/2
}

__global__ void qsetup(const float* __restrict__ params,   // (3,4,3)
                       const float* __restrict__ W,        // (4,4)
                       const float* __restrict__ bvec)     // (4,)
{
    __shared__ float Ur[16][17];
    __shared__ float Ui[16][17];
    __shared__ float sG[12][8];            // per-gate Rot matrix (r,i x 4)
    __shared__ float sA[4][16][16];        // A_k full symmetric
    __shared__ float sS[4][4][4][9];       // stage-1 partial transform
    __shared__ float sDt[4][9][9];         // D_k[u][v]

    const int t = threadIdx.x;
    const int n = t >> 4, c = t & 15;

    // --- phase A: 12 Rot gate matrices ------------------------------------
    if (t < 12) {
        float phi = params[t * 3 + 0];
        float th  = params[t * 3 + 1];
        float om  = params[t * 3 + 2];
        float ct = cosf(0.5f * th), st = sinf(0.5f * th);
        float a  = 0.5f * (phi + om);
        float bb = 0.5f * (phi - om);
        float ca = cosf(a),  sa = sinf(a);
        float cb = cosf(bb), sb = sinf(bb);
        sG[t][0] =  ca * ct;  sG[t][1] = -sa * ct;   // m00
        sG[t][2] = -cb * st;  sG[t][3] = -sb * st;   // m01
        sG[t][4] =  cb * st;  sG[t][5] = -sb * st;   // m10
        sG[t][6] =  ca * ct;  sG[t][7] =  sa * ct;   // m11
    }
    Ur[n][c] = (n == c) ? 1.0f : 0.0f;
    Ui[n][c] = 0.0f;
    __syncthreads();

    // --- phase B: apply gates to all 16 columns (gather style) ------------
    #pragma unroll
    for (int l = 0; l < 3; ++l) {
        #pragma unroll
        for (int w = 0; w < 4; ++w) {
            const int mask = 8 >> w;                 // wire 0 = MSB of row idx
            const float* g = sG[l * 4 + w];
            float xr = Ur[n][c], xi = Ui[n][c];
            float yr = Ur[n ^ mask][c], yi = Ui[n ^ mask][c];
            float nr, ni;
            if (!(n & mask)) {   // new[n0] = m00*x0 + m01*x1
                nr = g[0]*xr - g[1]*xi + g[2]*yr - g[3]*yi;
                ni = g[0]*xi + g[1]*xr + g[2]*yi + g[3]*yr;
            } else {             // new[n1] = m10*x0 + m11*x1  (y holds x0)
                nr = g[4]*yr - g[5]*yi + g[6]*xr - g[7]*xi;
                ni = g[4]*yi + g[5]*yr + g[6]*xi + g[7]*xr;
            }
            __syncthreads();
            Ur[n][c] = nr; Ui[n][c] = ni;
            __syncthreads();
        }
        // composed permutation of the layer's 4 sequential CNOTs:
        // out[n] = in[f0(f1(f2(f3(n))))], f_w(m) = (m & cm) ? m^tm : m
        const int r = (l % 3) + 1;
        int m = n;
        #pragma unroll
        for (int w = 3; w >= 0; --w) {
            const int cm = 8 >> w, tm = 8 >> ((w + r) & 3);
            if (m & cm) m ^= tm;
        }
        float vr = Ur[m][c], vi = Ui[m][c];
        __syncthreads();
        Ur[n][c] = vr; Ui[n][c] = vi;
        __syncthreads();
    }

    // --- phase C: A_k[i][j] = sum_w W[k][w] * Re(U^H Z_w U)[i][j] ----------
    {
        const int i = n, j = c;
        float M[4] = {0.f, 0.f, 0.f, 0.f};
        #pragma unroll
        for (int nn = 0; nn < 16; ++nn) {
            float v = Ur[nn][i] * Ur[nn][j] + Ui[nn][i] * Ui[nn][j];
            #pragma unroll
            for (int w = 0; w < 4; ++w)
                M[w] += (nn & (8 >> w)) ? -v : v;
        }
        #pragma unroll
        for (int k = 0; k < 4; ++k) {
            float acc = 0.0f;
            #pragma unroll
            for (int w = 0; w < 4; ++w) acc += W[k * 4 + w] * M[w];
            sA[k][i][j] = acc;
        }
    }
    __syncthreads();

    // --- phase D stage 1: contract wires 2,3 ------------------------------
    for (int idx = t; idx < 576; idx += 256) {
        int k   = idx / 144;
        int rem = idx - k * 144;
        int i01 = rem / 36;
        int r2  = rem - i01 * 36;
        int j01 = r2 / 9;
        int v   = r2 - j01 * 9;
        int a2 = v / 3, a3 = v - a2 * 3;
        float acc = 0.0f;
        #pragma unroll
        for (int i23 = 0; i23 < 4; ++i23)
            #pragma unroll
            for (int j23 = 0; j23 < 4; ++j23) {
                float e = Ecoef(i23 >> 1, j23 >> 1, a2) * Ecoef(i23 & 1, j23 & 1, a3);
                acc += e * sA[k][i01 * 4 + i23][j01 * 4 + j23];
            }
        sS[k][i01][j01][v] = acc;
    }
    __syncthreads();

    // --- phase D stage 2: contract wires 0,1; fold bias --------------------
    for (int idx = t; idx < 324; idx += 256) {
        int k  = idx / 81;
        int uv = idx - k * 81;
        int u  = uv / 9;
        int v  = uv - u * 9;
        int a0 = u / 3, a1 = u - a0 * 3;
        float acc = 0.0f;
        #pragma unroll
        for (int i01 = 0; i01 < 4; ++i01)
            #pragma unroll
            for (int j01 = 0; j01 < 4; ++j01) {
                float e = Ecoef(i01 >> 1, j01 >> 1, a0) * Ecoef(i01 & 1, j01 & 1, a1);
                acc += e * sS[k][i01][j01][v];
            }
        if (u == 0 && v == 0) acc += bvec[k];
        sDt[k][u][v] = acc;
    }
    __syncthreads();

    // --- pack: slot (u,vp): half0=(D0[v],D0[v+1],D1[v],D1[v+1]) half1=(D2,D3)
    if (t < 45) {
        int u = t / 5, vp = t - u * 5;
        int v = 2 * vp;
        bool pad = (vp == 4);
        float4* gd = reinterpret_cast<float4*>(g_D);
        gd[t * 2 + 0] = make_float4(sDt[0][u][v], pad ? 0.f : sDt[0][u][v + 1],
                                    sDt[1][u][v], pad ? 0.f : sDt[1][u][v + 1]);
        gd[t * 2 + 1] = make_float4(sDt[2][u][v], pad ? 0.f : sDt[2][u][v + 1],
                                    sDt[3][u][v], pad ? 0.f : sDt[3][u][v + 1]);
    }
}

// Build one patch's packed monomial vectors (m01 broadcast pairs, m23 v-pairs).
struct Patch {
    unsigned long long m01b[9];
    unsigned long long m23p[5];
    unsigned long long acc[4];
};

__device__ __forceinline__ void patch_init(Patch& P, const float* __restrict__ x, int gid)
{
    int b  = gid / 196;
    int p  = gid - b * 196;
    int pr = p / 14;
    int pc = p - pr * 14;

    const float* img = x + b * 784 + pr * 56 + pc * 2;
    float2 r0 = *reinterpret_cast<const float2*>(img);
    float2 r1 = *reinterpret_cast<const float2*>(img + 28);

    float C0, S0, C1, S1, C2, S2, C3, S3;
    __sincosf(r0.x, &S0, &C0);
    __sincosf(r0.y, &S1, &C1);
    __sincosf(r1.x, &S2, &C2);
    __sincosf(r1.y, &S3, &C3);

    float m01[9] = { 1.0f, C1, S1, C0, C0 * C1, C0 * S1, S0, S0 * C1, S0 * S1 };
    float m23[9] = { 1.0f, C3, S3, C2, C2 * C3, C2 * S3, S2, S2 * C3, S2 * S3 };

    #pragma unroll
    for (int u = 0; u < 9; ++u) PACK_F32X2(P.m01b[u], m01[u], m01[u]);
    #pragma unroll
    for (int vp = 0; vp < 4; ++vp) PACK_F32X2(P.m23p[vp], m23[2 * vp], m23[2 * vp + 1]);
    float z = 0.0f;
    PACK_F32X2(P.m23p[4], m23[8], z);
    #pragma unroll
    for (int k = 0; k < 4; ++k) P.acc[k] = 0ULL;
}

__device__ __forceinline__ float4 patch_result(const Patch& P)
{
    float l0, h0, l1, h1, l2, h2, l3, h3;
    UNPACK_F32X2(l0, h0, P.acc[0]);
    UNPACK_F32X2(l1, h1, P.acc[1]);
    UNPACK_F32X2(l2, h2, P.acc[2]);
    UNPACK_F32X2(l3, h3, P.acc[3]);
    return make_float4(l0 + h0, l1 + h1, l2 + h2, l3 + h3);
}

__global__ void __launch_bounds__(256) qmain(const float* __restrict__ x,
                                             float* __restrict__ out,
                                             int half, int total)
{
    __shared__ ulonglong2 sD[90];
    for (int i = threadIdx.x; i < 90; i += 256)
        sD[i] = reinterpret_cast<const ulonglong2*>(g_D)[i];
    __syncthreads();

    int g0 = blockIdx.x * blockDim.x + threadIdx.x;
    if (g0 >= half) return;
    int g1 = g0 + half;
    bool has1 = (g1 < total);

    Patch P0, P1;
    patch_init(P0, x, g0);
    patch_init(P1, x, has1 ? g1 : g0);

    #pragma unroll
    for (int u = 0; u < 9; ++u) {
        #pragma unroll
        for (int vp = 0; vp < 5; ++vp) {
            const int s = u * 5 + vp;
            ulonglong2 wa = sD[s * 2 + 0];
            ulonglong2 wb = sD[s * 2 + 1];
            unsigned long long t0, t1;
            MUL_F32X2(t0, P0.m01b[u], P0.m23p[vp]);
            MUL_F32X2(t1, P1.m01b[u], P1.m23p[vp]);
            FMA_F32X2(P0.acc[0], wa.x, t0, P0.acc[0]);
            FMA_F32X2(P1.acc[0], wa.x, t1, P1.acc[0]);
            FMA_F32X2(P0.acc[1], wa.y, t0, P0.acc[1]);
            FMA_F32X2(P1.acc[1], wa.y, t1, P1.acc[1]);
            FMA_F32X2(P0.acc[2], wb.x, t0, P0.acc[2]);
            FMA_F32X2(P1.acc[2], wb.x, t1, P1.acc[2]);
            FMA_F32X2(P0.acc[3], wb.y, t0, P0.acc[3]);
            FMA_F32X2(P1.acc[3], wb.y, t1, P1.acc[3]);
        }
    }

    reinterpret_cast<float4*>(out)[g0] = patch_result(P0);
    if (has1)
        reinterpret_cast<float4*>(out)[g1] = patch_result(P1);
}

extern "C" void kernel_launch(void* const* d_in, const int* in_sizes, int n_in,
                              void* d_out, int out_size)
{
    const float* x      = (const float*)d_in[0];   // (B,1,28,28)
    const float* params = (const float*)d_in[1];   // (3,4,3)
    const float* W      = (const float*)d_in[2];   // (4,4)
    const float* bvec   = (const float*)d_in[3];   // (4,)
    float* out = (float*)d_out;                    // (B, 784)

    int total = in_sizes[0] / 4;                   // B*196 patches
    int half  = (total + 1) / 2;

    qsetup<<<1, 256>>>(params, W, bvec);
    qmain<<<(half + 255) / 256, 256>>>(x, out, half, total);
}

// round 6
// speedup vs baseline: 2.1572x; 1.1001x over previous
#include <cuda_runtime.h>
#include <math.h>

// ============================================================================
// QuanvolutionFilter via fixed-unitary reduction + monomial (double-angle)
// basis + packed f32x2 FMA + 2 patches/thread + __constant__ coefficients.
//
//   out_k(patch) = m01^T D_k m23 ,   m01 = {1,C0,S0}x{1,C1,S1},
//                                    m23 = {1,C2,S2}x{1,C3,S3},  C=cos(a),S=sin(a)
//   D_k (9x9, padded to 9x10) built once from the circuit unitary U and W,b,
//   then copied into constant memory (uniform-const port, no L1 traffic).
// ============================================================================

#define PACK_F32X2(out, lo, hi) \
    asm("mov.b64 %0, {%1, %2};" : "=l"(out) : "f"(lo), "f"(hi))
#define UNPACK_F32X2(lo, hi, in) \
    asm("mov.b64 {%0, %1}, %2;" : "=f"(lo), "=f"(hi) : "l"(in))
#define MUL_F32X2(out, a, b) \
    asm("mul.rn.f32x2 %0, %1, %2;" : "=l"(out) : "l"(a), "l"(b))
#define FMA_F32X2(d, a, b, c) \
    asm("fma.rn.f32x2 %0, %1, %2, %3;" : "=l"(d) : "l"(a), "l"(b), "l"(c))

// packed coefficients: 45 (u,vp) slots x 2 ulonglong2:
//   slot half0 = (D0[v],D0[v+1],D1[v],D1[v+1]), half1 = (D2..,D3..)
__device__ __align__(16) float g_D[45 * 8];
__constant__ ulonglong2 cD[90];

// E[f][f'][alpha]: coefficient of monomial {1, cos a, sin a}[alpha] in the
// half-angle product p(f,f'), f,f' in {0=cos(a/2),1=sin(a/2)}.
__device__ __forceinline__ float Ecoef(int f, int fp, int al) {
    if (al == 2) return (f != fp) ? 0.5f : 0.0f;   // cs -> sin(a)/2
    if (f != fp) return 0.0f;
    if (al == 0) return 0.5f;                       // cc,ss -> 1/2
    return f ? -0.5f : 0.5f;                        // cc -> +cos/2, ss -> -cos/2
}

__global__ void qsetup(const float* __restrict__ params,   // (3,4,3)
                       const float* __restrict__ W,        // (4,4)
                       const float* __restrict__ bvec)     // (4,)
{
    __shared__ float Ur[16][17];
    __shared__ float Ui[16][17];
    __shared__ float sG[12][8];            // per-gate Rot matrix (r,i x 4)
    __shared__ float sA[4][16][16];        // A_k full symmetric
    __shared__ float sS[4][4][4][9];       // stage-1 partial transform
    __shared__ float sDt[4][9][9];         // D_k[u][v]

    const int t = threadIdx.x;
    const int n = t >> 4, c = t & 15;

    // --- phase A: 12 Rot gate matrices ------------------------------------
    if (t < 12) {
        float phi = params[t * 3 + 0];
        float th  = params[t * 3 + 1];
        float om  = params[t * 3 + 2];
        float ct = cosf(0.5f * th), st = sinf(0.5f * th);
        float a  = 0.5f * (phi + om);
        float bb = 0.5f * (phi - om);
        float ca = cosf(a),  sa = sinf(a);
        float cb = cosf(bb), sb = sinf(bb);
        sG[t][0] =  ca * ct;  sG[t][1] = -sa * ct;   // m00
        sG[t][2] = -cb * st;  sG[t][3] = -sb * st;   // m01
        sG[t][4] =  cb * st;  sG[t][5] = -sb * st;   // m10
        sG[t][6] =  ca * ct;  sG[t][7] =  sa * ct;   // m11
    }
    Ur[n][c] = (n == c) ? 1.0f : 0.0f;
    Ui[n][c] = 0.0f;
    __syncthreads();

    // --- phase B: apply gates to all 16 columns (gather style) ------------
    #pragma unroll
    for (int l = 0; l < 3; ++l) {
        #pragma unroll
        for (int w = 0; w < 4; ++w) {
            const int mask = 8 >> w;                 // wire 0 = MSB of row idx
            const float* g = sG[l * 4 + w];
            float xr = Ur[n][c], xi = Ui[n][c];
            float yr = Ur[n ^ mask][c], yi = Ui[n ^ mask][c];
            float nr, ni;
            if (!(n & mask)) {   // new[n0] = m00*x0 + m01*x1
                nr = g[0]*xr - g[1]*xi + g[2]*yr - g[3]*yi;
                ni = g[0]*xi + g[1]*xr + g[2]*yi + g[3]*yr;
            } else {             // new[n1] = m10*x0 + m11*x1  (y holds x0)
                nr = g[4]*yr - g[5]*yi + g[6]*xr - g[7]*xi;
                ni = g[4]*yi + g[5]*yr + g[6]*xi + g[7]*xr;
            }
            __syncthreads();
            Ur[n][c] = nr; Ui[n][c] = ni;
            __syncthreads();
        }
        // composed permutation of the layer's 4 sequential CNOTs:
        // out[n] = in[f0(f1(f2(f3(n))))], f_w(m) = (m & cm) ? m^tm : m
        const int r = (l % 3) + 1;
        int m = n;
        #pragma unroll
        for (int w = 3; w >= 0; --w) {
            const int cm = 8 >> w, tm = 8 >> ((w + r) & 3);
            if (m & cm) m ^= tm;
        }
        float vr = Ur[m][c], vi = Ui[m][c];
        __syncthreads();
        Ur[n][c] = vr; Ui[n][c] = vi;
        __syncthreads();
    }

    // --- phase C: A_k[i][j] = sum_w W[k][w] * Re(U^H Z_w U)[i][j] ----------
    {
        const int i = n, j = c;
        float M[4] = {0.f, 0.f, 0.f, 0.f};
        #pragma unroll
        for (int nn = 0; nn < 16; ++nn) {
            float v = Ur[nn][i] * Ur[nn][j] + Ui[nn][i] * Ui[nn][j];
            #pragma unroll
            for (int w = 0; w < 4; ++w)
                M[w] += (nn & (8 >> w)) ? -v : v;
        }
        #pragma unroll
        for (int k = 0; k < 4; ++k) {
            float acc = 0.0f;
            #pragma unroll
            for (int w = 0; w < 4; ++w) acc += W[k * 4 + w] * M[w];
            sA[k][i][j] = acc;
        }
    }
    __syncthreads();

    // --- phase D stage 1: contract wires 2,3 ------------------------------
    for (int idx = t; idx < 576; idx += 256) {
        int k   = idx / 144;
        int rem = idx - k * 144;
        int i01 = rem / 36;
        int r2  = rem - i01 * 36;
        int j01 = r2 / 9;
        int v   = r2 - j01 * 9;
        int a2 = v / 3, a3 = v - a2 * 3;
        float acc = 0.0f;
        #pragma unroll
        for (int i23 = 0; i23 < 4; ++i23)
            #pragma unroll
            for (int j23 = 0; j23 < 4; ++j23) {
                float e = Ecoef(i23 >> 1, j23 >> 1, a2) * Ecoef(i23 & 1, j23 & 1, a3);
                acc += e * sA[k][i01 * 4 + i23][j01 * 4 + j23];
            }
        sS[k][i01][j01][v] = acc;
    }
    __syncthreads();

    // --- phase D stage 2: contract wires 0,1; fold bias --------------------
    for (int idx = t; idx < 324; idx += 256) {
        int k  = idx / 81;
        int uv = idx - k * 81;
        int u  = uv / 9;
        int v  = uv - u * 9;
        int a0 = u / 3, a1 = u - a0 * 3;
        float acc = 0.0f;
        #pragma unroll
        for (int i01 = 0; i01 < 4; ++i01)
            #pragma unroll
            for (int j01 = 0; j01 < 4; ++j01) {
                float e = Ecoef(i01 >> 1, j01 >> 1, a0) * Ecoef(i01 & 1, j01 & 1, a1);
                acc += e * sS[k][i01][j01][v];
            }
        if (u == 0 && v == 0) acc += bvec[k];
        sDt[k][u][v] = acc;
    }
    __syncthreads();

    // --- pack: slot (u,vp): half0=(D0[v],D0[v+1],D1[v],D1[v+1]) half1=(D2,D3)
    if (t < 45) {
        int u = t / 5, vp = t - u * 5;
        int v = 2 * vp;
        bool pad = (vp == 4);
        float4* gd = reinterpret_cast<float4*>(g_D);
        gd[t * 2 + 0] = make_float4(sDt[0][u][v], pad ? 0.f : sDt[0][u][v + 1],
                                    sDt[1][u][v], pad ? 0.f : sDt[1][u][v + 1]);
        gd[t * 2 + 1] = make_float4(sDt[2][u][v], pad ? 0.f : sDt[2][u][v + 1],
                                    sDt[3][u][v], pad ? 0.f : sDt[3][u][v + 1]);
    }
}

// per-patch packed monomial state: f0/f1 broadcast pairs, m23 v-pairs.
struct Patch {
    unsigned long long f0b[3];   // {(1,1),(C0,C0),(S0,S0)}
    unsigned long long f1b[3];   // {(1,1),(C1,C1),(S1,S1)}
    unsigned long long m23p[5];  // (m23[0],m23[1]),(2,3),(4,5),(6,7),(8,0)
    unsigned long long acc[4];
};

__device__ __forceinline__ void patch_init(Patch& P, const float* __restrict__ x, int gid)
{
    int b  = gid / 196;
    int p  = gid - b * 196;
    int pr = p / 14;
    int pc = p - pr * 14;

    const float* img = x + b * 784 + pr * 56 + pc * 2;
    float2 r0 = *reinterpret_cast<const float2*>(img);
    float2 r1 = *reinterpret_cast<const float2*>(img + 28);

    float C0, S0, C1, S1, C2, S2, C3, S3;
    __sincosf(r0.x, &S0, &C0);
    __sincosf(r0.y, &S1, &C1);
    __sincosf(r1.x, &S2, &C2);
    __sincosf(r1.y, &S3, &C3);

    float one = 1.0f, z = 0.0f;
    PACK_F32X2(P.f0b[0], one, one);
    PACK_F32X2(P.f0b[1], C0, C0);
    PACK_F32X2(P.f0b[2], S0, S0);
    PACK_F32X2(P.f1b[0], one, one);
    PACK_F32X2(P.f1b[1], C1, C1);
    PACK_F32X2(P.f1b[2], S1, S1);

    float m23[9] = { 1.0f, C3, S3, C2, C2 * C3, C2 * S3, S2, S2 * C3, S2 * S3 };
    #pragma unroll
    for (int vp = 0; vp < 4; ++vp) PACK_F32X2(P.m23p[vp], m23[2 * vp], m23[2 * vp + 1]);
    PACK_F32X2(P.m23p[4], m23[8], z);

    #pragma unroll
    for (int k = 0; k < 4; ++k) P.acc[k] = 0ULL;
}

__device__ __forceinline__ float4 patch_result(const Patch& P)
{
    float l0, h0, l1, h1, l2, h2, l3, h3;
    UNPACK_F32X2(l0, h0, P.acc[0]);
    UNPACK_F32X2(l1, h1, P.acc[1]);
    UNPACK_F32X2(l2, h2, P.acc[2]);
    UNPACK_F32X2(l3, h3, P.acc[3]);
    return make_float4(l0 + h0, l1 + h1, l2 + h2, l3 + h3);
}

__global__ void __launch_bounds__(256, 4) qmain(const float* __restrict__ x,
                                                float* __restrict__ out,
                                                int half, int total)
{
    int g0 = blockIdx.x * blockDim.x + threadIdx.x;
    if (g0 >= half) return;
    int g1 = g0 + half;
    bool has1 = (g1 < total);

    Patch P0, P1;
    patch_init(P0, x, g0);
    patch_init(P1, x, has1 ? g1 : g0);

    #pragma unroll
    for (int u = 0; u < 9; ++u) {
        const int ui = u / 3, uj = u - 3 * (u / 3);
        unsigned long long m01_0, m01_1;
        MUL_F32X2(m01_0, P0.f0b[ui], P0.f1b[uj]);
        MUL_F32X2(m01_1, P1.f0b[ui], P1.f1b[uj]);
        #pragma unroll
        for (int vp = 0; vp < 5; ++vp) {
            const int s = u * 5 + vp;
            ulonglong2 wa = cD[s * 2 + 0];   // uniform-const port (LDCU)
            ulonglong2 wb = cD[s * 2 + 1];
            unsigned long long t0, t1;
            MUL_F32X2(t0, m01_0, P0.m23p[vp]);
            MUL_F32X2(t1, m01_1, P1.m23p[vp]);
            FMA_F32X2(P0.acc[0], wa.x, t0, P0.acc[0]);
            FMA_F32X2(P1.acc[0], wa.x, t1, P1.acc[0]);
            FMA_F32X2(P0.acc[1], wa.y, t0, P0.acc[1]);
            FMA_F32X2(P1.acc[1], wa.y, t1, P1.acc[1]);
            FMA_F32X2(P0.acc[2], wb.x, t0, P0.acc[2]);
            FMA_F32X2(P1.acc[2], wb.x, t1, P1.acc[2]);
            FMA_F32X2(P0.acc[3], wb.y, t0, P0.acc[3]);
            FMA_F32X2(P1.acc[3], wb.y, t1, P1.acc[3]);
        }
    }

    reinterpret_cast<float4*>(out)[g0] = patch_result(P0);
    if (has1)
        reinterpret_cast<float4*>(out)[g1] = patch_result(P1);
}

extern "C" void kernel_launch(void* const* d_in, const int* in_sizes, int n_in,
                              void* d_out, int out_size)
{
    const float* x      = (const float*)d_in[0];   // (B,1,28,28)
    const float* params = (const float*)d_in[1];   // (3,4,3)
    const float* W      = (const float*)d_in[2];   // (4,4)
    const float* bvec   = (const float*)d_in[3];   // (4,)
    float* out = (float*)d_out;                    // (B, 784)

    int total = in_sizes[0] / 4;                   // B*196 patches
    int half  = (total + 1) / 2;

    qsetup<<<1, 256>>>(params, W, bvec);

    // stage the device-computed coefficients into constant memory
    // (D2D async memcpy: graph-capturable, no allocation)
    void* gptr = nullptr;
    cudaGetSymbolAddress(&gptr, g_D);
    cudaMemcpyToSymbolAsync(cD, gptr, sizeof(float) * 360, 0,
                            cudaMemcpyDeviceToDevice, 0);

    qmain<<<(half + 255) / 256, 256>>>(x, out, half, total);
}

// round 7
// speedup vs baseline: 2.3679x; 1.0977x over previous
#include <cuda_runtime.h>
#include <math.h>

// ============================================================================
// QuanvolutionFilter via fixed-unitary reduction + monomial (double-angle)
// basis; lanes of f32x2 = (patch0, patch1); coefficients are broadcast pairs
// in __constant__ memory.
//
//   out_k(patch) = sum_{u,v} D_k[u][v] * m01[u] * m23[v]
//   m01 = {1,C0,S0}x{1,C1,S1}, m23 = {1,C2,S2}x{1,C3,S3}
//   unit entries (u=0 / v=0 / (0,0)) handled without multiplies.
// ============================================================================

#define PACK_F32X2(out, lo, hi) \
    asm("mov.b64 %0, {%1, %2};" : "=l"(out) : "f"(lo), "f"(hi))
#define UNPACK_F32X2(lo, hi, in) \
    asm("mov.b64 {%0, %1}, %2;" : "=f"(lo), "=f"(hi) : "l"(in))
#define MUL_F32X2(out, a, b) \
    asm("mul.rn.f32x2 %0, %1, %2;" : "=l"(out) : "l"(a), "l"(b))
#define FMA_F32X2(d, a, b, c) \
    asm("fma.rn.f32x2 %0, %1, %2, %3;" : "=l"(d) : "l"(a), "l"(b), "l"(c))

// coefficient slot (u*9+v): two float4 = (D0,D0,D1,D1),(D2,D2,D3,D3)
__device__ __align__(16) float g_D[81 * 8];
__constant__ ulonglong2 cD[162];

// E[f][f'][alpha]: coefficient of monomial {1, cos a, sin a}[alpha] in the
// half-angle product p(f,f'), f,f' in {0=cos(a/2),1=sin(a/2)}.
__device__ __forceinline__ float Ecoef(int f, int fp, int al) {
    if (al == 2) return (f != fp) ? 0.5f : 0.0f;   // cs -> sin(a)/2
    if (f != fp) return 0.0f;
    if (al == 0) return 0.5f;                       // cc,ss -> 1/2
    return f ? -0.5f : 0.5f;                        // cc -> +cos/2, ss -> -cos/2
}

__global__ void qsetup(const float* __restrict__ params,   // (3,4,3)
                       const float* __restrict__ W,        // (4,4)
                       const float* __restrict__ bvec)     // (4,)
{
    __shared__ float Ur[16][17];
    __shared__ float Ui[16][17];
    __shared__ float sG[12][8];            // per-gate Rot matrix (r,i x 4)
    __shared__ float sA[4][16][16];        // A_k full symmetric
    __shared__ float sS[4][4][4][9];       // stage-1 partial transform
    __shared__ float sDt[4][9][9];         // D_k[u][v]

    const int t = threadIdx.x;
    const int n = t >> 4, c = t & 15;

    // --- phase A: 12 Rot gate matrices ------------------------------------
    if (t < 12) {
        float phi = params[t * 3 + 0];
        float th  = params[t * 3 + 1];
        float om  = params[t * 3 + 2];
        float ct = cosf(0.5f * th), st = sinf(0.5f * th);
        float a  = 0.5f * (phi + om);
        float bb = 0.5f * (phi - om);
        float ca = cosf(a),  sa = sinf(a);
        float cb = cosf(bb), sb = sinf(bb);
        sG[t][0] =  ca * ct;  sG[t][1] = -sa * ct;   // m00
        sG[t][2] = -cb * st;  sG[t][3] = -sb * st;   // m01
        sG[t][4] =  cb * st;  sG[t][5] = -sb * st;   // m10
        sG[t][6] =  ca * ct;  sG[t][7] =  sa * ct;   // m11
    }
    Ur[n][c] = (n == c) ? 1.0f : 0.0f;
    Ui[n][c] = 0.0f;
    __syncthreads();

    // --- phase B: apply gates to all 16 columns (gather style) ------------
    #pragma unroll
    for (int l = 0; l < 3; ++l) {
        #pragma unroll
        for (int w = 0; w < 4; ++w) {
            const int mask = 8 >> w;                 // wire 0 = MSB of row idx
            const float* g = sG[l * 4 + w];
            float xr = Ur[n][c], xi = Ui[n][c];
            float yr = Ur[n ^ mask][c], yi = Ui[n ^ mask][c];
            float nr, ni;
            if (!(n & mask)) {   // new[n0] = m00*x0 + m01*x1
                nr = g[0]*xr - g[1]*xi + g[2]*yr - g[3]*yi;
                ni = g[0]*xi + g[1]*xr + g[2]*yi + g[3]*yr;
            } else {             // new[n1] = m10*x0 + m11*x1  (y holds x0)
                nr = g[4]*yr - g[5]*yi + g[6]*xr - g[7]*xi;
                ni = g[4]*yi + g[5]*yr + g[6]*xi + g[7]*xr;
            }
            __syncthreads();
            Ur[n][c] = nr; Ui[n][c] = ni;
            __syncthreads();
        }
        // composed permutation of the layer's 4 sequential CNOTs
        const int r = (l % 3) + 1;
        int m = n;
        #pragma unroll
        for (int w = 3; w >= 0; --w) {
            const int cm = 8 >> w, tm = 8 >> ((w + r) & 3);
            if (m & cm) m ^= tm;
        }
        float vr = Ur[m][c], vi = Ui[m][c];
        __syncthreads();
        Ur[n][c] = vr; Ui[n][c] = vi;
        __syncthreads();
    }

    // --- phase C: A_k[i][j] = sum_w W[k][w] * Re(U^H Z_w U)[i][j] ----------
    {
        const int i = n, j = c;
        float M[4] = {0.f, 0.f, 0.f, 0.f};
        #pragma unroll
        for (int nn = 0; nn < 16; ++nn) {
            float v = Ur[nn][i] * Ur[nn][j] + Ui[nn][i] * Ui[nn][j];
            #pragma unroll
            for (int w = 0; w < 4; ++w)
                M[w] += (nn & (8 >> w)) ? -v : v;
        }
        #pragma unroll
        for (int k = 0; k < 4; ++k) {
            float acc = 0.0f;
            #pragma unroll
            for (int w = 0; w < 4; ++w) acc += W[k * 4 + w] * M[w];
            sA[k][i][j] = acc;
        }
    }
    __syncthreads();

    // --- phase D stage 1: contract wires 2,3 ------------------------------
    for (int idx = t; idx < 576; idx += 256) {
        int k   = idx / 144;
        int rem = idx - k * 144;
        int i01 = rem / 36;
        int r2  = rem - i01 * 36;
        int j01 = r2 / 9;
        int v   = r2 - j01 * 9;
        int a2 = v / 3, a3 = v - a2 * 3;
        float acc = 0.0f;
        #pragma unroll
        for (int i23 = 0; i23 < 4; ++i23)
            #pragma unroll
            for (int j23 = 0; j23 < 4; ++j23) {
                float e = Ecoef(i23 >> 1, j23 >> 1, a2) * Ecoef(i23 & 1, j23 & 1, a3);
                acc += e * sA[k][i01 * 4 + i23][j01 * 4 + j23];
            }
        sS[k][i01][j01][v] = acc;
    }
    __syncthreads();

    // --- phase D stage 2: contract wires 0,1; fold bias --------------------
    for (int idx = t; idx < 324; idx += 256) {
        int k  = idx / 81;
        int uv = idx - k * 81;
        int u  = uv / 9;
        int v  = uv - u * 9;
        int a0 = u / 3, a1 = u - a0 * 3;
        float acc = 0.0f;
        #pragma unroll
        for (int i01 = 0; i01 < 4; ++i01)
            #pragma unroll
            for (int j01 = 0; j01 < 4; ++j01) {
                float e = Ecoef(i01 >> 1, j01 >> 1, a0) * Ecoef(i01 & 1, j01 & 1, a1);
                acc += e * sS[k][i01][j01][v];
            }
        if (u == 0 && v == 0) acc += bvec[k];
        sDt[k][u][v] = acc;
    }
    __syncthreads();

    // --- pack duplicated broadcast pairs: slot t=(u*9+v) -------------------
    if (t < 81) {
        int u = t / 9, v = t - u * 9;
        float4* gd = reinterpret_cast<float4*>(g_D);
        gd[t * 2 + 0] = make_float4(sDt[0][u][v], sDt[0][u][v],
                                    sDt[1][u][v], sDt[1][u][v]);
        gd[t * 2 + 1] = make_float4(sDt[2][u][v], sDt[2][u][v],
                                    sDt[3][u][v], sDt[3][u][v]);
    }
}

__device__ __forceinline__ void patch_angles(const float* __restrict__ x, int gid,
                                             float* C, float* S)
{
    int b  = gid / 196;
    int p  = gid - b * 196;
    int pr = p / 14;
    int pc = p - pr * 14;
    const float* img = x + b * 784 + pr * 56 + pc * 2;
    float2 r0 = *reinterpret_cast<const float2*>(img);
    float2 r1 = *reinterpret_cast<const float2*>(img + 28);
    __sincosf(r0.x, &S[0], &C[0]);
    __sincosf(r0.y, &S[1], &C[1]);
    __sincosf(r1.x, &S[2], &C[2]);
    __sincosf(r1.y, &S[3], &C[3]);
}

__global__ void __launch_bounds__(256, 5) qmain(const float* __restrict__ x,
                                                float* __restrict__ out,
                                                int half, int total)
{
    int g0 = blockIdx.x * blockDim.x + threadIdx.x;
    if (g0 >= half) return;
    int g1 = g0 + half;
    bool has1 = (g1 < total);

    float C0[4], S0[4], C1[4], S1[4];           // [wire], per patch
    patch_angles(x, g0, C0, S0);
    patch_angles(x, has1 ? g1 : g0, C1, S1);

    // packed lanes = (patch0, patch1)
    unsigned long long f0c, f0s, f1c, f1s;      // cos/sin of a0, a1
    PACK_F32X2(f0c, C0[0], C1[0]);
    PACK_F32X2(f0s, S0[0], S1[0]);
    PACK_F32X2(f1c, C0[1], C1[1]);
    PACK_F32X2(f1s, S0[1], S1[1]);

    // m23[v], v=1..8 : {C3, S3, C2, C2C3, C2S3, S2, S2C3, S2S3}
    float m3a[8] = { C0[3], S0[3], C0[2], C0[2]*C0[3], C0[2]*S0[3],
                     S0[2], S0[2]*C0[3], S0[2]*S0[3] };
    float m3b[8] = { C1[3], S1[3], C1[2], C1[2]*C1[3], C1[2]*S1[3],
                     S1[2], S1[2]*C1[3], S1[2]*S1[3] };
    unsigned long long m23b[8];
    #pragma unroll
    for (int v = 0; v < 8; ++v) PACK_F32X2(m23b[v], m3a[v], m3b[v]);

    // acc init = D[0][0] (bias folded) since tp(0,0) = 1
    unsigned long long acc0, acc1, acc2, acc3;
    {
        ulonglong2 w0 = cD[0], w1 = cD[1];
        acc0 = w0.x; acc1 = w0.y; acc2 = w1.x; acc3 = w1.y;
    }

    // u = 0 row: tp = m23[v]
    #pragma unroll
    for (int v = 1; v < 9; ++v) {
        ulonglong2 wa = cD[v * 2 + 0];
        ulonglong2 wb = cD[v * 2 + 1];
        unsigned long long tp = m23b[v - 1];
        FMA_F32X2(acc0, wa.x, tp, acc0);
        FMA_F32X2(acc1, wa.y, tp, acc1);
        FMA_F32X2(acc2, wb.x, tp, acc2);
        FMA_F32X2(acc3, wb.y, tp, acc3);
    }

    #pragma unroll
    for (int u = 1; u < 9; ++u) {
        unsigned long long m01u;
        if      (u == 1) m01u = f1c;
        else if (u == 2) m01u = f1s;
        else if (u == 3) m01u = f0c;
        else if (u == 4) { MUL_F32X2(m01u, f0c, f1c); }
        else if (u == 5) { MUL_F32X2(m01u, f0c, f1s); }
        else if (u == 6) m01u = f0s;
        else if (u == 7) { MUL_F32X2(m01u, f0s, f1c); }
        else             { MUL_F32X2(m01u, f0s, f1s); }

        // v = 0: tp = m01[u]
        {
            ulonglong2 wa = cD[u * 18 + 0];
            ulonglong2 wb = cD[u * 18 + 1];
            FMA_F32X2(acc0, wa.x, m01u, acc0);
            FMA_F32X2(acc1, wa.y, m01u, acc1);
            FMA_F32X2(acc2, wb.x, m01u, acc2);
            FMA_F32X2(acc3, wb.y, m01u, acc3);
        }
        #pragma unroll
        for (int v = 1; v < 9; ++v) {
            ulonglong2 wa = cD[(u * 9 + v) * 2 + 0];
            ulonglong2 wb = cD[(u * 9 + v) * 2 + 1];
            unsigned long long tp;
            MUL_F32X2(tp, m01u, m23b[v - 1]);
            FMA_F32X2(acc0, wa.x, tp, acc0);
            FMA_F32X2(acc1, wa.y, tp, acc1);
            FMA_F32X2(acc2, wb.x, tp, acc2);
            FMA_F32X2(acc3, wb.y, tp, acc3);
        }
    }

    float o00, o01, o10, o11, o20, o21, o30, o31;
    UNPACK_F32X2(o00, o01, acc0);
    UNPACK_F32X2(o10, o11, acc1);
    UNPACK_F32X2(o20, o21, acc2);
    UNPACK_F32X2(o30, o31, acc3);

    reinterpret_cast<float4*>(out)[g0] = make_float4(o00, o10, o20, o30);
    if (has1)
        reinterpret_cast<float4*>(out)[g1] = make_float4(o01, o11, o21, o31);
}

extern "C" void kernel_launch(void* const* d_in, const int* in_sizes, int n_in,
                              void* d_out, int out_size)
{
    const float* x      = (const float*)d_in[0];   // (B,1,28,28)
    const float* params = (const float*)d_in[1];   // (3,4,3)
    const float* W      = (const float*)d_in[2];   // (4,4)
    const float* bvec   = (const float*)d_in[3];   // (4,)
    float* out = (float*)d_out;                    // (B, 784)

    int total = in_sizes[0] / 4;                   // B*196 patches
    int half  = (total + 1) / 2;

    qsetup<<<1, 256>>>(params, W, bvec);

    // stage device-computed coefficients into constant memory (D2D, capturable)
    void* gptr = nullptr;
    cudaGetSymbolAddress(&gptr, g_D);
    cudaMemcpyToSymbolAsync(cD, gptr, sizeof(float) * 81 * 8, 0,
                            cudaMemcpyDeviceToDevice, 0);

    qmain<<<(half + 255) / 256, 256>>>(x, out, half, total);
}